// round 2
// baseline (speedup 1.0000x reference)
#include <cuda_runtime.h>

#define NQ    12
#define DEPTH 4
#define HID   64
#define NPAR  144   // DEPTH*NQ*3
#define THREADS 256

// Flat index convention (matches JAX ref): qubit q <-> bit (11-q) of the
// 12-bit basis index. Thread t owns amplitudes i = (t<<4)|k, k in [0,16).

__global__ __launch_bounds__(THREADS, 2)
void qgen_kernel(const float* __restrict__ noise,
                 const float* __restrict__ W1, const float* __restrict__ b1,
                 const float* __restrict__ W2, const float* __restrict__ b2,
                 const float* __restrict__ W3, const float* __restrict__ b3,
                 const float* __restrict__ W4, const float* __restrict__ b4,
                 float* __restrict__ out)
{
    __shared__ float2 ex[4096];     // exchange buffer, slot(i) = (i&15)*256 + (i>>4)
    __shared__ float4 gmat[48];     // per gate: (alpha.re, alpha.im, beta.re, beta.im)
    __shared__ float  s_nz[12];
    __shared__ float  s_h[64];
    __shared__ float  s_par[NPAR];
    __shared__ float  s_meas[12];
    __shared__ float  s_wsum[8][12];
    __shared__ float  s_h2[64];
    __shared__ int    s_fk[16];

    const int t   = threadIdx.x;
    const int bId = blockIdx.x;

    // ---- load noise row + CNOT-ring permutation table for low 4 bits ----
    if (t < 12) s_nz[t] = noise[bId * 12 + t];
    if (t < 16) {
        int d = t;
        #pragma unroll
        for (int q = 0; q < 12; q++) {
            int bc = 11 - q;
            int bt = 11 - ((q + 1) % 12);
            d ^= ((d >> bc) & 1) << bt;
        }
        s_fk[t] = d;
    }
    __syncthreads();

    // ---- MLP1: h = tanh(noise @ W1 + b1) ----
    if (t < 64) {
        float acc = b1[t];
        #pragma unroll
        for (int m = 0; m < 12; m++) acc += s_nz[m] * W1[m * 64 + t];
        s_h[t] = tanhf(acc);
    }
    __syncthreads();

    // ---- MLP2: circuit params = h @ W2 + b2 ----
    if (t < NPAR) {
        float acc = b2[t];
        #pragma unroll 8
        for (int j = 0; j < 64; j++) acc += s_h[j] * W2[j * NPAR + t];
        s_par[t] = acc;
    }
    __syncthreads();

    // ---- per-gate SU(2) matrix: U = RZ(c) RY(b) RX(a) = [[a, b],[-b*, a*]] ----
    if (t < 48) {
        float a = s_par[t * 3 + 0], b = s_par[t * 3 + 1], c = s_par[t * 3 + 2];
        float ca, sa, cb, sb, cc, sc;
        sincosf(0.5f * a, &sa, &ca);
        sincosf(0.5f * b, &sb, &cb);
        sincosf(0.5f * c, &sc, &cc);
        float x = cb * ca, y = sb * sa, z = sb * ca, w = cb * sa;
        float4 g;
        g.x =  cc * x + sc * y;    // alpha.re
        g.y =  cc * y - sc * x;    // alpha.im
        g.z = -(cc * z + sc * w);  // beta.re
        g.w =  sc * z - cc * w;    // beta.im
        gmat[t] = g;
    }
    __syncthreads();   // <<< FIX: gmat must be visible to ALL threads before gate 0

    // per-thread base of the linear CNOT-ring map: f((t<<4)|k) = f(t<<4) ^ f(k)
    int fbase = t << 4;
    #pragma unroll
    for (int q = 0; q < 12; q++) {
        int bc = 11 - q;
        int bt = 11 - ((q + 1) % 12);
        fbase ^= ((fbase >> bc) & 1) << bt;
    }

    // ---- init |0...0> ----
    float2 amp[16];
    #pragma unroll
    for (int k = 0; k < 16; k++) amp[k] = make_float2(0.f, 0.f);
    if (t == 0) amp[0].x = 1.0f;

    // ---- circuit layers ----
    #pragma unroll 1
    for (int l = 0; l < DEPTH; l++) {
        // q = 0..2 : index bit 11..9 = tid bit 7..5 -> SMEM exchange
        #pragma unroll
        for (int q = 0; q < 3; q++) {
            float4 g = gmat[l * 12 + q];
            const int tb = (11 - q) - 4;       // 7,6,5
            const int mybit = (t >> tb) & 1;
            __syncthreads();
            #pragma unroll
            for (int k = 0; k < 16; k++) ex[k * 256 + t] = amp[k];
            __syncthreads();
            const int tp = t ^ (1 << tb);
            #pragma unroll
            for (int k = 0; k < 16; k++) {
                float2 o = ex[k * 256 + tp];
                float2 m = amp[k];
                float2 r;
                if (mybit == 0) {      // new0 = alpha*m + beta*o
                    r.x = g.x * m.x - g.y * m.y + g.z * o.x - g.w * o.y;
                    r.y = g.x * m.y + g.y * m.x + g.z * o.y + g.w * o.x;
                } else {               // new1 = -beta* * o + alpha* * m
                    r.x = -g.z * o.x - g.w * o.y + g.x * m.x + g.y * m.y;
                    r.y = -g.z * o.y + g.w * o.x + g.x * m.y - g.y * m.x;
                }
                amp[k] = r;
            }
        }

        // q = 3..7 : index bit 8..4 = lane bit 4..0 -> shuffle exchange
        #pragma unroll
        for (int q = 3; q < 8; q++) {
            float4 g = gmat[l * 12 + q];
            const int tb = (11 - q) - 4;       // 4..0
            const int mybit = (t >> tb) & 1;
            const int lmask = 1 << tb;
            #pragma unroll
            for (int k = 0; k < 16; k++) {
                float2 m = amp[k];
                float2 o;
                o.x = __shfl_xor_sync(0xffffffffu, m.x, lmask);
                o.y = __shfl_xor_sync(0xffffffffu, m.y, lmask);
                float2 r;
                if (mybit == 0) {
                    r.x = g.x * m.x - g.y * m.y + g.z * o.x - g.w * o.y;
                    r.y = g.x * m.y + g.y * m.x + g.z * o.y + g.w * o.x;
                } else {
                    r.x = -g.z * o.x - g.w * o.y + g.x * m.x + g.y * m.y;
                    r.y = -g.z * o.y + g.w * o.x + g.x * m.y - g.y * m.x;
                }
                amp[k] = r;
            }
        }

        // q = 8..11 : index bit 3..0 -> purely register-local pairs
        #pragma unroll
        for (int q = 8; q < 12; q++) {
            float4 g = gmat[l * 12 + q];
            const int mask = 1 << (11 - q);    // 8,4,2,1
            #pragma unroll
            for (int k0 = 0; k0 < 16; k0++) {
                if (k0 & mask) continue;
                const int k1 = k0 | mask;
                float2 a0 = amp[k0], a1 = amp[k1];
                float2 r0, r1;
                r0.x = g.x * a0.x - g.y * a0.y + g.z * a1.x - g.w * a1.y;
                r0.y = g.x * a0.y + g.y * a0.x + g.z * a1.y + g.w * a1.x;
                r1.x = -g.z * a0.x - g.w * a0.y + g.x * a1.x + g.y * a1.y;
                r1.y = -g.z * a0.y + g.w * a0.x + g.x * a1.y - g.y * a1.x;
                amp[k0] = r0;
                amp[k1] = r1;
            }
        }

        // ---- CNOT ring = fixed linear permutation, one SMEM scatter ----
        __syncthreads();
        #pragma unroll
        for (int k = 0; k < 16; k++) {
            int d = fbase ^ s_fk[k];
            ex[(d & 15) * 256 + (d >> 4)] = amp[k];
        }
        __syncthreads();
        #pragma unroll
        for (int k = 0; k < 16; k++) amp[k] = ex[k * 256 + t];
    }

    // ---- <Z_q> : per-thread signed probability sums ----
    float P = 0.f, S0 = 0.f, S1 = 0.f, S2 = 0.f, S3 = 0.f;
    #pragma unroll
    for (int k = 0; k < 16; k++) {
        float p = amp[k].x * amp[k].x + amp[k].y * amp[k].y;
        P  += p;
        S0 += (k & 1) ? -p : p;
        S1 += (k & 2) ? -p : p;
        S2 += (k & 4) ? -p : p;
        S3 += (k & 8) ? -p : p;
    }
    float c[12];
    #pragma unroll
    for (int q = 0; q < 8; q++) c[q] = ((t >> (7 - q)) & 1) ? -P : P;
    c[8] = S3; c[9] = S2; c[10] = S1; c[11] = S0;

    #pragma unroll
    for (int s = 16; s >= 1; s >>= 1) {
        #pragma unroll
        for (int q = 0; q < 12; q++)
            c[q] += __shfl_xor_sync(0xffffffffu, c[q], s);
    }
    const int warp = t >> 5, lane = t & 31;
    if (lane == 0) {
        #pragma unroll
        for (int q = 0; q < 12; q++) s_wsum[warp][q] = c[q];
    }
    __syncthreads();
    if (t < 12) {
        float m = 0.f;
        #pragma unroll
        for (int w = 0; w < 8; w++) m += s_wsum[w][t];
        s_meas[t] = m;
    }
    __syncthreads();

    // ---- MLP3: h2 = tanh(meas @ W3 + b3) ----
    if (t < 64) {
        float acc = b3[t];
        #pragma unroll
        for (int q = 0; q < 12; q++) acc += s_meas[q] * W3[q * 64 + t];
        s_h2[t] = tanhf(acc);
    }
    __syncthreads();

    // ---- out = h2 @ W4 + b4 ----
    if (t < 2) {
        float acc = b4[t];
        #pragma unroll 8
        for (int j = 0; j < 64; j++) acc += s_h2[j] * W4[j * 2 + t];
        out[bId * 2 + t] = acc;
    }
}

extern "C" void kernel_launch(void* const* d_in, const int* in_sizes, int n_in,
                              void* d_out, int out_size)
{
    (void)n_in; (void)out_size;
    const float* noise = (const float*)d_in[0];
    const float* W1    = (const float*)d_in[1];
    const float* b1    = (const float*)d_in[2];
    const float* W2    = (const float*)d_in[3];
    const float* b2    = (const float*)d_in[4];
    const float* W3    = (const float*)d_in[5];
    const float* b3    = (const float*)d_in[6];
    const float* W4    = (const float*)d_in[7];
    const float* b4    = (const float*)d_in[8];
    float* out = (float*)d_out;

    const int B = in_sizes[0] / NQ;
    qgen_kernel<<<B, THREADS>>>(noise, W1, b1, W2, b2, W3, b3, W4, b4, out);
}

// round 3
// speedup vs baseline: 1.8931x; 1.8931x over previous
#include <cuda_runtime.h>

typedef unsigned long long u64;

#define NQ    12
#define DEPTH 4
#define NPAR  144
#define THREADS 256

// ---------- f32x2 packed helpers ----------
__device__ __forceinline__ u64 f2fma(u64 a, u64 b, u64 c) {
    u64 d; asm("fma.rn.f32x2 %0,%1,%2,%3;" : "=l"(d) : "l"(a), "l"(b), "l"(c)); return d;
}
__device__ __forceinline__ u64 f2mul(u64 a, u64 b) {
    u64 d; asm("mul.rn.f32x2 %0,%1,%2;" : "=l"(d) : "l"(a), "l"(b)); return d;
}
__device__ __forceinline__ u64 pk(float lo, float hi) {
    u64 r; asm("mov.b64 %0,{%1,%2};" : "=l"(r) : "f"(lo), "f"(hi)); return r;
}
__device__ __forceinline__ void upk(u64 v, float& lo, float& hi) {
    asm("mov.b64 {%0,%1},%2;" : "=f"(lo), "=f"(hi) : "l"(v));
}
__device__ __forceinline__ u64 f2swap(u64 v) {
    float lo, hi; upk(v, lo, hi); return pk(hi, lo);
}

// ---------- CNOT-ring permutation (matches reference gate order) ----------
__device__ __forceinline__ int perm12(int s) {
    int d = s;
    #pragma unroll
    for (int q = 0; q < 12; q++) {
        int bc = 11 - q, bt = 11 - ((q + 1) % 12);
        d ^= ((d >> bc) & 1) << bt;
    }
    return d;
}
// byte offset of amp d in the exchange arrays (GF2-linear in d's bits)
__device__ __forceinline__ int laddr(int d) {
    return ((d >> 5) << 7) | ((((d >> 1) & 15) ^ ((d >> 5) & 15)) << 3) | ((d & 1) << 2);
}
// byte-offset delta contributed by m (= i[11:8]) in layout-B addressing
__device__ __forceinline__ int bmoff(int m) {
    return (m << 10) | ((m & 1) << 6);
}

// Load packed gate constants: gpk[gi*12 + 0..6] = PX,PY,NY,PZ,NZ,PW,NW
#define LOADC(gi)                                                     \
    const u64* rec = gpk + (gi) * 12;                                 \
    ulonglong2 q01 = *(const ulonglong2*)(rec);                       \
    ulonglong2 q23 = *(const ulonglong2*)(rec + 2);                   \
    ulonglong2 q45 = *(const ulonglong2*)(rec + 4);                   \
    u64 PX = q01.x, PY = q01.y, NY = q23.x, PZ = q23.y;               \
    u64 NZ = q45.x, PW = q45.y, NW = rec[6];

__global__ __launch_bounds__(THREADS, 2)
void qgen_kernel(const float* __restrict__ noise,
                 const float* __restrict__ W1, const float* __restrict__ b1,
                 const float* __restrict__ W2, const float* __restrict__ b2,
                 const float* __restrict__ W3, const float* __restrict__ b3,
                 const float* __restrict__ W4, const float* __restrict__ b4,
                 float* __restrict__ out)
{
    __shared__ __align__(16) float exR[4096];   // re parts, unit-swizzled
    __shared__ __align__(16) float exI[4096];   // im parts
    __shared__ __align__(16) u64   gpk[48 * 12]; // packed gate consts
    __shared__ float s_nz[12];
    __shared__ float s_h[64];
    __shared__ float s_par[NPAR];
    __shared__ float s_meas[12];
    __shared__ float s_wsum[8][12];
    __shared__ float s_h2[64];

    const int t   = threadIdx.x;
    const int bId = blockIdx.x;

    if (t < 12) s_nz[t] = noise[bId * 12 + t];
    __syncthreads();

    // ---- MLP1 ----
    if (t < 64) {
        float acc = b1[t];
        #pragma unroll
        for (int m = 0; m < 12; m++) acc += s_nz[m] * W1[m * 64 + t];
        s_h[t] = tanhf(acc);
    }
    __syncthreads();

    // ---- MLP2 ----
    if (t < NPAR) {
        float acc = b2[t];
        #pragma unroll 8
        for (int j = 0; j < 64; j++) acc += s_h[j] * W2[j * NPAR + t];
        s_par[t] = acc;
    }
    __syncthreads();

    // ---- per-gate SU(2): U = RZ(c)RY(b)RX(a) = [[gx+i gy, gz+i gw],[-(gz-i gw), gx-i gy]]
    if (t < 48) {
        float a = s_par[t * 3 + 0], b = s_par[t * 3 + 1], c = s_par[t * 3 + 2];
        float ca, sa, cb, sb, cc, sc;
        sincosf(0.5f * a, &sa, &ca);
        sincosf(0.5f * b, &sb, &cb);
        sincosf(0.5f * c, &sc, &cc);
        float x = cb * ca, y = sb * sa, z = sb * ca, w = cb * sa;
        float gx =  cc * x + sc * y;
        float gy =  cc * y - sc * x;
        float gz = -(cc * z + sc * w);
        float gw =  sc * z - cc * w;
        u64* r = gpk + t * 12;
        r[0]  = pk(gx, gx);  r[1] = pk(gy, gy);  r[2] = pk(-gy, -gy);
        r[3]  = pk(gz, gz);  r[4] = pk(-gz, -gz);
        r[5]  = pk(gw, gw);  r[6] = pk(-gw, -gw);
        r[8]  = pk(-gy, gy); r[9] = pk(gy, -gy); r[10] = pk(gz, -gz);
    }

    // ---- per-thread exchange addresses ----
    // Layout A: thread t = i[11:4], regs = i[3:0] = (p<<1)|lane; u64 unit holds (i,i^1)
    const int AbU = ((t >> 1) << 4) | (((t & 1) << 3) ^ ((t >> 1) & 15));  // ^p for reg p
    // Layout B: thread u=t = i[7:0], regs = i[11:8] = (pB<<1)|laneB
    const int uh  = t >> 5;
    const int Bb  = (uh << 7) | ((((t >> 1) & 15) ^ uh) << 3) | ((t & 1) << 2);
    // permutation scatter base: addr(m,u) = puA ^ laddr(perm12(m<<8))
    const int puA = laddr(perm12(t));

    u64* exR64 = (u64*)exR;
    u64* exI64 = (u64*)exI;

    // ---- init |0..0> ----
    u64 Re[8], Im[8];
    #pragma unroll
    for (int p = 0; p < 8; p++) { Re[p] = 0ull; Im[p] = 0ull; }
    if (t == 0) Re[0] = pk(1.0f, 0.0f);

    __syncthreads();   // gpk visible to all

    #pragma unroll 1
    for (int l = 0; l < DEPTH; l++) {
        // ---- q=11 : intra-register (lane) gate ----
        {
            const u64* rec = gpk + (l * 12 + 11) * 12;
            u64 PX = rec[0], PWv = rec[5], NWv = rec[6];
            ulonglong2 mm = *(const ulonglong2*)(rec + 8);
            u64 MY = mm.x, MYr = mm.y, MZ = rec[10];
            #pragma unroll
            for (int p = 0; p < 8; p++) {
                u64 R = Re[p], I = Im[p];
                u64 Rs = f2swap(R), Is = f2swap(I);
                Re[p] = f2fma(NWv, Is, f2fma(MZ, Rs, f2fma(MY,  I, f2mul(PX, R))));
                Im[p] = f2fma(PWv, Rs, f2fma(MZ, Is, f2fma(MYr, R, f2mul(PX, I))));
            }
        }
        // ---- q=10,9,8 : register-pair lanewise gates (p ^ 1,2,4) ----
        #pragma unroll
        for (int qq = 0; qq < 3; qq++) {
            const int gi = l * 12 + 10 - qq;
            const int mask = 1 << qq;
            LOADC(gi)
            #pragma unroll
            for (int p0 = 0; p0 < 8; p0++) {
                if (p0 & mask) continue;
                const int p1 = p0 | mask;
                u64 aR = Re[p0], aI = Im[p0], bR = Re[p1], bI = Im[p1];
                Re[p0] = f2fma(NW, bI, f2fma(PZ, bR, f2fma(NY, aI, f2mul(PX, aR))));
                Im[p0] = f2fma(PW, bR, f2fma(PZ, bI, f2fma(PY, aR, f2mul(PX, aI))));
                Re[p1] = f2fma(NW, aI, f2fma(NZ, aR, f2fma(PY, bI, f2mul(PX, bR))));
                Im[p1] = f2fma(PW, aR, f2fma(NZ, aI, f2fma(NY, bR, f2mul(PX, bI))));
            }
        }
        // ---- q=7..3 : lane-shuffle gates (thread bits 0..4) ----
        #pragma unroll
        for (int tb = 0; tb < 5; tb++) {
            const int gi = l * 12 + 7 - tb;
            const int lm = 1 << tb;
            LOADC(gi)
            const int mybit = (t >> tb) & 1;
            u64 Ya = mybit ? PY : NY;
            u64 Yb = mybit ? NY : PY;
            u64 Zc = mybit ? NZ : PZ;
            #pragma unroll
            for (int p = 0; p < 8; p++) {
                u64 mR = Re[p], mI = Im[p];
                u64 oR = __shfl_xor_sync(0xffffffffu, mR, lm);
                u64 oI = __shfl_xor_sync(0xffffffffu, mI, lm);
                Re[p] = f2fma(NW, oI, f2fma(Zc, oR, f2fma(Ya, mI, f2mul(PX, mR))));
                Im[p] = f2fma(PW, oR, f2fma(Zc, oI, f2fma(Yb, mR, f2mul(PX, mI))));
            }
        }

        // ---- transpose A -> B ----
        __syncthreads();
        #pragma unroll
        for (int p = 0; p < 8; p++) {
            exR64[AbU ^ p] = Re[p];
            exI64[AbU ^ p] = Im[p];
        }
        __syncthreads();
        #pragma unroll
        for (int pB = 0; pB < 8; pB++) {
            const int a0 = Bb ^ bmoff(2 * pB);
            const int a1 = Bb ^ bmoff(2 * pB + 1);
            float r0 = *(const float*)((const char*)exR + a0);
            float r1 = *(const float*)((const char*)exR + a1);
            float i0 = *(const float*)((const char*)exI + a0);
            float i1 = *(const float*)((const char*)exI + a1);
            Re[pB] = pk(r0, r1);
            Im[pB] = pk(i0, i1);
        }

        // ---- q=2,1,0 : lanewise in layout B (pB ^ 1,2,4) ----
        #pragma unroll
        for (int qq = 0; qq < 3; qq++) {
            const int gi = l * 12 + 2 - qq;
            const int mask = 1 << qq;
            LOADC(gi)
            #pragma unroll
            for (int p0 = 0; p0 < 8; p0++) {
                if (p0 & mask) continue;
                const int p1 = p0 | mask;
                u64 aR = Re[p0], aI = Im[p0], bR = Re[p1], bI = Im[p1];
                Re[p0] = f2fma(NW, bI, f2fma(PZ, bR, f2fma(NY, aI, f2mul(PX, aR))));
                Im[p0] = f2fma(PW, bR, f2fma(PZ, bI, f2fma(PY, aR, f2mul(PX, aI))));
                Re[p1] = f2fma(NW, aI, f2fma(NZ, aR, f2fma(PY, bI, f2mul(PX, bR))));
                Im[p1] = f2fma(PW, aR, f2fma(NZ, aI, f2fma(NY, bR, f2mul(PX, bI))));
            }
        }

        // ---- CNOT-ring permutation scatter, back to layout A ----
        __syncthreads();
        #pragma unroll
        for (int pB = 0; pB < 8; pB++) {
            float r0, r1, i0v, i1v;
            upk(Re[pB], r0, r1);
            upk(Im[pB], i0v, i1v);
            const int a0 = puA ^ laddr(perm12((2 * pB) << 8));
            const int a1 = puA ^ laddr(perm12((2 * pB + 1) << 8));
            *(float*)((char*)exR + a0) = r0;  *(float*)((char*)exI + a0) = i0v;
            *(float*)((char*)exR + a1) = r1;  *(float*)((char*)exI + a1) = i1v;
        }
        __syncthreads();
        #pragma unroll
        for (int p = 0; p < 8; p++) {
            Re[p] = exR64[AbU ^ p];
            Im[p] = exI64[AbU ^ p];
        }
    }

    // ---- <Z_q> ----
    float P = 0.f, S0 = 0.f, S1 = 0.f, S2 = 0.f, S3 = 0.f;
    #pragma unroll
    for (int p = 0; p < 8; p++) {
        u64 p2 = f2fma(Im[p], Im[p], f2mul(Re[p], Re[p]));
        float pe, po; upk(p2, pe, po);
        float s = pe + po;
        P  += s;
        S0 += pe - po;               // qubit 11 (i bit0 = lane)
        S1 += (p & 1) ? -s : s;      // qubit 10
        S2 += (p & 2) ? -s : s;      // qubit 9
        S3 += (p & 4) ? -s : s;      // qubit 8
    }
    float c[12];
    #pragma unroll
    for (int q = 0; q < 8; q++) c[q] = ((t >> (7 - q)) & 1) ? -P : P;
    c[8] = S3; c[9] = S2; c[10] = S1; c[11] = S0;

    #pragma unroll
    for (int s = 16; s >= 1; s >>= 1) {
        #pragma unroll
        for (int q = 0; q < 12; q++)
            c[q] += __shfl_xor_sync(0xffffffffu, c[q], s);
    }
    const int warp = t >> 5, lane = t & 31;
    if (lane == 0) {
        #pragma unroll
        for (int q = 0; q < 12; q++) s_wsum[warp][q] = c[q];
    }
    __syncthreads();
    if (t < 12) {
        float m = 0.f;
        #pragma unroll
        for (int w = 0; w < 8; w++) m += s_wsum[w][t];
        s_meas[t] = m;
    }
    __syncthreads();

    // ---- MLP3 ----
    if (t < 64) {
        float acc = b3[t];
        #pragma unroll
        for (int q = 0; q < 12; q++) acc += s_meas[q] * W3[q * 64 + t];
        s_h2[t] = tanhf(acc);
    }
    __syncthreads();

    // ---- out ----
    if (t < 2) {
        float acc = b4[t];
        #pragma unroll 8
        for (int j = 0; j < 64; j++) acc += s_h2[j] * W4[j * 2 + t];
        out[bId * 2 + t] = acc;
    }
}

extern "C" void kernel_launch(void* const* d_in, const int* in_sizes, int n_in,
                              void* d_out, int out_size)
{
    (void)n_in; (void)out_size;
    const float* noise = (const float*)d_in[0];
    const float* W1    = (const float*)d_in[1];
    const float* b1    = (const float*)d_in[2];
    const float* W2    = (const float*)d_in[3];
    const float* b2    = (const float*)d_in[4];
    const float* W3    = (const float*)d_in[5];
    const float* b3    = (const float*)d_in[6];
    const float* W4    = (const float*)d_in[7];
    const float* b4    = (const float*)d_in[8];
    float* out = (float*)d_out;

    const int B = in_sizes[0] / NQ;
    qgen_kernel<<<B, THREADS>>>(noise, W1, b1, W2, b2, W3, b3, W4, b4, out);
}

// round 4
// speedup vs baseline: 2.1846x; 1.1540x over previous
#include <cuda_runtime.h>

typedef unsigned long long u64;

#define NQ    12
#define DEPTH 4
#define NPAR  144
#define THREADS 256

// ---------- f32x2 packed helpers ----------
__device__ __forceinline__ u64 f2fma(u64 a, u64 b, u64 c) {
    u64 d; asm("fma.rn.f32x2 %0,%1,%2,%3;" : "=l"(d) : "l"(a), "l"(b), "l"(c)); return d;
}
__device__ __forceinline__ u64 f2mul(u64 a, u64 b) {
    u64 d; asm("mul.rn.f32x2 %0,%1,%2;" : "=l"(d) : "l"(a), "l"(b)); return d;
}
__device__ __forceinline__ u64 pk(float lo, float hi) {
    u64 r; asm("mov.b64 %0,{%1,%2};" : "=l"(r) : "f"(lo), "f"(hi)); return r;
}
__device__ __forceinline__ void upk(u64 v, float& lo, float& hi) {
    asm("mov.b64 {%0,%1},%2;" : "=f"(lo), "=f"(hi) : "l"(v));
}
__device__ __forceinline__ u64 f2swap(u64 v) {
    float lo, hi; upk(v, lo, hi); return pk(hi, lo);
}

struct c2 { float r, i; };
__device__ __forceinline__ c2 cmul(c2 a, c2 b) {
    c2 o; o.r = a.r * b.r - a.i * b.i; o.i = a.r * b.i + a.i * b.r; return o;
}

// ---------- CNOT-ring permutation (matches reference gate order) ----------
__device__ __forceinline__ int perm12(int s) {
    int d = s;
    #pragma unroll
    for (int q = 0; q < 12; q++) {
        int bc = 11 - q, bt = 11 - ((q + 1) % 12);
        d ^= ((d >> bc) & 1) << bt;
    }
    return d;
}
// byte offset of amp d in the exchange arrays (GF2-linear in d's bits)
__device__ __forceinline__ int laddr(int d) {
    return ((d >> 5) << 7) | ((((d >> 1) & 15) ^ ((d >> 5) & 15)) << 3) | ((d & 1) << 2);
}
// byte-offset delta contributed by m (= i[11:8]) in layout-B addressing
__device__ __forceinline__ int bmoff(int m) {
    return (m << 10) | ((m & 1) << 6);
}

#define LOADC(gi)                                                     \
    const u64* rec = gpk + (gi) * 12;                                 \
    ulonglong2 q01 = *(const ulonglong2*)(rec);                       \
    ulonglong2 q23 = *(const ulonglong2*)(rec + 2);                   \
    ulonglong2 q45 = *(const ulonglong2*)(rec + 4);                   \
    u64 PX = q01.x, PY = q01.y, NY = q23.x, PZ = q23.y;               \
    u64 NZ = q45.x, PW = q45.y, NW = rec[6];

__global__ __launch_bounds__(THREADS, 2)
void qgen_kernel(const float* __restrict__ noise,
                 const float* __restrict__ W1, const float* __restrict__ b1,
                 const float* __restrict__ W2, const float* __restrict__ b2,
                 const float* __restrict__ W3, const float* __restrict__ b3,
                 const float* __restrict__ W4, const float* __restrict__ b4,
                 float* __restrict__ out)
{
    __shared__ __align__(16) float exR[4096];
    __shared__ __align__(16) float exI[4096];
    __shared__ __align__(16) u64   gpk[48 * 12];
    __shared__ float2 s_v[12][2];     // layer-0 product-state vectors
    __shared__ float s_nz[12];
    __shared__ float s_h[64];
    __shared__ float s_par[NPAR];
    __shared__ float s_meas[12];
    __shared__ float s_wsum[8][12];
    __shared__ float s_h2[64];

    const int t   = threadIdx.x;
    const int bId = blockIdx.x;

    if (t < 12) s_nz[t] = noise[bId * 12 + t];
    __syncthreads();

    // ---- MLP1 ----
    if (t < 64) {
        float acc = b1[t];
        #pragma unroll
        for (int m = 0; m < 12; m++) acc += s_nz[m] * W1[m * 64 + t];
        s_h[t] = tanhf(acc);
    }
    __syncthreads();

    // ---- MLP2 ----
    if (t < NPAR) {
        float acc = b2[t];
        #pragma unroll 8
        for (int j = 0; j < 64; j++) acc += s_h[j] * W2[j * NPAR + t];
        s_par[t] = acc;
    }
    __syncthreads();

    // ---- per-gate SU(2): U = RZ(c)RY(b)RX(a) = [[gx+igy, gz+igw],[-(gz-igw), gx-igy]]
    if (t < 48) {
        float a = s_par[t * 3 + 0], b = s_par[t * 3 + 1], c = s_par[t * 3 + 2];
        float ca, sa, cb, sb, cc, sc;
        sincosf(0.5f * a, &sa, &ca);
        sincosf(0.5f * b, &sb, &cb);
        sincosf(0.5f * c, &sc, &cc);
        float x = cb * ca, y = sb * sa, z = sb * ca, w = cb * sa;
        float gx =  cc * x + sc * y;
        float gy =  cc * y - sc * x;
        float gz = -(cc * z + sc * w);
        float gw =  sc * z - cc * w;
        u64* r = gpk + t * 12;
        r[0]  = pk(gx, gx);  r[1] = pk(gy, gy);  r[2] = pk(-gy, -gy);
        r[3]  = pk(gz, gz);  r[4] = pk(-gz, -gz);
        r[5]  = pk(gw, gw);  r[6] = pk(-gw, -gw);
        r[8]  = pk(-gy, gy); r[9] = pk(gy, -gy); r[10] = pk(gz, -gz);
        if (t < 12) {   // layer-0 gate: U|0> = (gx+igy, -(gz-igw)) = (alpha, -beta*)
            s_v[t][0] = make_float2(gx, gy);
            s_v[t][1] = make_float2(-gz, gw);
        }
    }

    // ---- per-thread exchange addresses ----
    // Layout A: thread t = i[11:4], regs = i[3:0] = (p<<1)|lane
    const int AbU = ((t >> 1) << 4) | (((t & 1) << 3) ^ ((t >> 1) & 15));
    // Layout B: thread u=t = i[7:0], regs = i[11:8] = (pB<<1)|laneB
    const int uh  = t >> 5;
    const int Bb  = (uh << 7) | ((((t >> 1) & 15) ^ uh) << 3) | ((t & 1) << 2);
    const int puA = laddr(perm12(t));

    u64* exR64 = (u64*)exR;
    u64* exI64 = (u64*)exI;

    __syncthreads();   // gpk + s_v visible

    // ---- layer 0 (gates + CNOT ring) via product-state synthesis ----
    // amp_A[i] = prod_q v_q[x_q], x = P^-1(i):
    //   x_0 = i11^i0, x_1 = i10^i11^i0, x_j = i(11-j)^i(12-j) (j>=2)
    u64 Re[8], Im[8];
    {
        c2 v[12][2];
        #pragma unroll
        for (int q = 0; q < 12; q++) {
            float2 a0 = s_v[q][0], a1 = s_v[q][1];
            v[q][0].r = a0.x; v[q][0].i = a0.y;
            v[q][1].r = a1.x; v[q][1].i = a1.y;
        }
        const int x2 = ((t >> 5) ^ (t >> 6)) & 1;
        const int x3 = ((t >> 4) ^ (t >> 5)) & 1;
        const int x4 = ((t >> 3) ^ (t >> 4)) & 1;
        const int x5 = ((t >> 2) ^ (t >> 3)) & 1;
        const int x6 = ((t >> 1) ^ (t >> 2)) & 1;
        const int x7 = ( t       ^ (t >> 1)) & 1;
        const int e0 = (t >> 7) & 1;                 // i11
        const int e1 = ((t >> 6) ^ (t >> 7)) & 1;    // i10^i11
        const int e4 = t & 1;                        // i4

        c2 base = cmul(cmul(cmul(v[2][x2], v[3][x3]), cmul(v[4][x4], v[5][x5])),
                       cmul(v[6][x6], v[7][x7]));
        c2 base2[2];
        base2[0] = cmul(base, v[8][e4]);
        base2[1] = cmul(base, v[8][e4 ^ 1]);

        c2 A[2];
        A[0] = cmul(v[0][e0],     v[1][e1]);         // k0 = 0
        A[1] = cmul(v[0][e0 ^ 1], v[1][e1 ^ 1]);     // k0 = 1
        c2 B[4];                                     // idx = k1k0, * v11[k0^k1]
        B[0] = cmul(A[0], v[11][0]);
        B[1] = cmul(A[1], v[11][1]);
        B[2] = cmul(A[0], v[11][1]);
        B[3] = cmul(A[1], v[11][0]);
        c2 C[8];                                     // * v10[k1^k2]
        #pragma unroll
        for (int k2 = 0; k2 < 2; k2++)
            #pragma unroll
            for (int j = 0; j < 4; j++)
                C[k2 * 4 + j] = cmul(B[j], v[10][((j >> 1) & 1) ^ k2]);
        // D = C * v9[k2^k3], amp = D * base2[k3]
        #pragma unroll
        for (int k3 = 0; k3 < 2; k3++)
            #pragma unroll
            for (int j = 0; j < 8; j += 2) {
                c2 d0 = cmul(cmul(C[j],     v[9][((j >> 2) & 1) ^ k3]), base2[k3]);
                c2 d1 = cmul(cmul(C[j + 1], v[9][(((j+1) >> 2) & 1) ^ k3]), base2[k3]);
                int p = (k3 * 8 + j) >> 1;
                Re[p] = pk(d0.r, d1.r);
                Im[p] = pk(d0.i, d1.i);
            }
    }

    // ---- layers 1..3 ----
    #pragma unroll 1
    for (int l = 1; l < DEPTH; l++) {
        // q=11 : intra-register (lane) gate
        {
            const u64* rec = gpk + (l * 12 + 11) * 12;
            u64 PX = rec[0], PWv = rec[5], NWv = rec[6];
            ulonglong2 mm = *(const ulonglong2*)(rec + 8);
            u64 MY = mm.x, MYr = mm.y, MZ = rec[10];
            #pragma unroll
            for (int p = 0; p < 8; p++) {
                u64 R = Re[p], I = Im[p];
                u64 Rs = f2swap(R), Is = f2swap(I);
                Re[p] = f2fma(NWv, Is, f2fma(MZ, Rs, f2fma(MY,  I, f2mul(PX, R))));
                Im[p] = f2fma(PWv, Rs, f2fma(MZ, Is, f2fma(MYr, R, f2mul(PX, I))));
            }
        }
        // q=10,9,8 : register-pair lanewise gates
        #pragma unroll
        for (int qq = 0; qq < 3; qq++) {
            const int gi = l * 12 + 10 - qq;
            const int mask = 1 << qq;
            LOADC(gi)
            #pragma unroll
            for (int p0 = 0; p0 < 8; p0++) {
                if (p0 & mask) continue;
                const int p1 = p0 | mask;
                u64 aR = Re[p0], aI = Im[p0], bR = Re[p1], bI = Im[p1];
                Re[p0] = f2fma(NW, bI, f2fma(PZ, bR, f2fma(NY, aI, f2mul(PX, aR))));
                Im[p0] = f2fma(PW, bR, f2fma(PZ, bI, f2fma(PY, aR, f2mul(PX, aI))));
                Re[p1] = f2fma(NW, aI, f2fma(NZ, aR, f2fma(PY, bI, f2mul(PX, bR))));
                Im[p1] = f2fma(PW, aR, f2fma(NZ, aI, f2fma(NY, bR, f2mul(PX, bI))));
            }
        }
        // q=7..3 : lane-shuffle gates
        #pragma unroll
        for (int tb = 0; tb < 5; tb++) {
            const int gi = l * 12 + 7 - tb;
            const int lm = 1 << tb;
            LOADC(gi)
            const int mybit = (t >> tb) & 1;
            u64 Ya = mybit ? PY : NY;
            u64 Yb = mybit ? NY : PY;
            u64 Zc = mybit ? NZ : PZ;
            #pragma unroll
            for (int p = 0; p < 8; p++) {
                u64 mR = Re[p], mI = Im[p];
                u64 oR = __shfl_xor_sync(0xffffffffu, mR, lm);
                u64 oI = __shfl_xor_sync(0xffffffffu, mI, lm);
                Re[p] = f2fma(NW, oI, f2fma(Zc, oR, f2fma(Ya, mI, f2mul(PX, mR))));
                Im[p] = f2fma(PW, oR, f2fma(Zc, oI, f2fma(Yb, mR, f2mul(PX, mI))));
            }
        }

        // transpose A -> B
        __syncthreads();
        #pragma unroll
        for (int p = 0; p < 8; p++) {
            exR64[AbU ^ p] = Re[p];
            exI64[AbU ^ p] = Im[p];
        }
        __syncthreads();
        #pragma unroll
        for (int pB = 0; pB < 8; pB++) {
            const int a0 = Bb ^ bmoff(2 * pB);
            const int a1 = Bb ^ bmoff(2 * pB + 1);
            float r0 = *(const float*)((const char*)exR + a0);
            float r1 = *(const float*)((const char*)exR + a1);
            float i0 = *(const float*)((const char*)exI + a0);
            float i1 = *(const float*)((const char*)exI + a1);
            Re[pB] = pk(r0, r1);
            Im[pB] = pk(i0, i1);
        }

        // q=2,1,0 : lanewise in layout B
        #pragma unroll
        for (int qq = 0; qq < 3; qq++) {
            const int gi = l * 12 + 2 - qq;
            const int mask = 1 << qq;
            LOADC(gi)
            #pragma unroll
            for (int p0 = 0; p0 < 8; p0++) {
                if (p0 & mask) continue;
                const int p1 = p0 | mask;
                u64 aR = Re[p0], aI = Im[p0], bR = Re[p1], bI = Im[p1];
                Re[p0] = f2fma(NW, bI, f2fma(PZ, bR, f2fma(NY, aI, f2mul(PX, aR))));
                Im[p0] = f2fma(PW, bR, f2fma(PZ, bI, f2fma(PY, aR, f2mul(PX, aI))));
                Re[p1] = f2fma(NW, aI, f2fma(NZ, aR, f2fma(PY, bI, f2mul(PX, bR))));
                Im[p1] = f2fma(PW, aR, f2fma(NZ, aI, f2fma(NY, bR, f2mul(PX, bI))));
            }
        }

        if (l == DEPTH - 1) break;   // last layer: CNOT ring folded into measurement signs

        // CNOT-ring permutation scatter, back to layout A
        __syncthreads();
        #pragma unroll
        for (int pB = 0; pB < 8; pB++) {
            float r0, r1, i0v, i1v;
            upk(Re[pB], r0, r1);
            upk(Im[pB], i0v, i1v);
            const int a0 = puA ^ laddr(perm12((2 * pB) << 8));
            const int a1 = puA ^ laddr(perm12((2 * pB + 1) << 8));
            *(float*)((char*)exR + a0) = r0;  *(float*)((char*)exI + a0) = i0v;
            *(float*)((char*)exR + a1) = r1;  *(float*)((char*)exI + a1) = i1v;
        }
        __syncthreads();
        #pragma unroll
        for (int p = 0; p < 8; p++) {
            Re[p] = exR64[AbU ^ p];
            Im[p] = exI64[AbU ^ p];
        }
    }

    // ---- <Z_q> in layout B with post-ring prefix-parity signs ----
    // Layout B: thread t = i[7:0] (x_4..x_11), regs m = i[11:8] (m3=x_0..m0=x_3),
    // packed lane = m bit0 = x_3.
    // x'_q(s) = x_0^..^x_q (q>=1); x'_0 = x_1^..^x_11.
    float T0 = 0.f, T1 = 0.f, T2 = 0.f, T3 = 0.f;
    #pragma unroll
    for (int pB = 0; pB < 8; pB++) {
        u64 p2 = f2fma(Im[pB], Im[pB], f2mul(Re[pB], Re[pB]));
        float pl, ph; upk(p2, pl, ph);
        float sm = pl + ph, df = pl - ph;
        T0 += (__popc(pB & 3) & 1) ? -df : df;   // q=0 m-part: m&0b0111
        T1 += (__popc(pB & 6) & 1) ? -sm : sm;   // q=1: m&0b1100
        T2 += (__popc(pB & 7) & 1) ? -sm : sm;   // q=2: m&0b1110
        T3 += (__popc(pB & 7) & 1) ? -df : df;   // q>=3: m&0b1111
    }
    float c[12];
    c[0] = (__popc(t) & 1) ? -T0 : T0;
    c[1] = T1; c[2] = T2; c[3] = T3;
    #pragma unroll
    for (int q = 4; q < 12; q++) {
        const int tmask = (0xFF << (11 - q)) & 0xFF;   // t bits for x_4..x_q
        c[q] = (__popc(t & tmask) & 1) ? -T3 : T3;
    }

    #pragma unroll
    for (int s = 16; s >= 1; s >>= 1) {
        #pragma unroll
        for (int q = 0; q < 12; q++)
            c[q] += __shfl_xor_sync(0xffffffffu, c[q], s);
    }
    const int warp = t >> 5, lane = t & 31;
    if (lane == 0) {
        #pragma unroll
        for (int q = 0; q < 12; q++) s_wsum[warp][q] = c[q];
    }
    __syncthreads();
    if (t < 12) {
        float m = 0.f;
        #pragma unroll
        for (int w = 0; w < 8; w++) m += s_wsum[w][t];
        s_meas[t] = m;
    }
    __syncthreads();

    // ---- MLP3 ----
    if (t < 64) {
        float acc = b3[t];
        #pragma unroll
        for (int q = 0; q < 12; q++) acc += s_meas[q] * W3[q * 64 + t];
        s_h2[t] = tanhf(acc);
    }
    __syncthreads();

    // ---- out ----
    if (t < 2) {
        float acc = b4[t];
        #pragma unroll 8
        for (int j = 0; j < 64; j++) acc += s_h2[j] * W4[j * 2 + t];
        out[bId * 2 + t] = acc;
    }
}

extern "C" void kernel_launch(void* const* d_in, const int* in_sizes, int n_in,
                              void* d_out, int out_size)
{
    (void)n_in; (void)out_size;
    const float* noise = (const float*)d_in[0];
    const float* W1    = (const float*)d_in[1];
    const float* b1    = (const float*)d_in[2];
    const float* W2    = (const float*)d_in[3];
    const float* b2    = (const float*)d_in[4];
    const float* W3    = (const float*)d_in[5];
    const float* b3    = (const float*)d_in[6];
    const float* W4    = (const float*)d_in[7];
    const float* b4    = (const float*)d_in[8];
    float* out = (float*)d_out;

    const int B = in_sizes[0] / NQ;
    qgen_kernel<<<B, THREADS>>>(noise, W1, b1, W2, b2, W3, b3, W4, b4, out);
}